// round 14
// baseline (speedup 1.0000x reference)
#include <cuda_runtime.h>

#define Bb   8
#define HW   1024
#define Cc   512
#define C4   128
#define NBLK 128
#define NTHR 512
// dynamic smem: conv_s[32][512] + q_s[32][512] + kC[32][512]  (192 KB)
#define DYN_BYTES (3 * 16384 * 4)

// ---------------- sync counters, one per 128-B line ---------------------------
struct alignas(128) Line { unsigned v; unsigned pad[31]; };
__device__ Line c_cs[8];    // colsum tickets per batch (16 each)
__device__ Line c_xs;       // xsum winners (8)
__device__ Line c_kp;       // stage1 arrivals (16)
__device__ Line c_wp;       // stage2 arrivals (16)
__device__ Line c_up;       // stage3 arrivals (16)
__device__ Line c_ep[8];    // epilogue arrivals per batch (16 each)
__device__ Line c_fin;      // 128 arrivals; 128th resets everything (never polled)
__device__ unsigned g_mnk[Bb] = {0xFFFFFFFFu,0xFFFFFFFFu,0xFFFFFFFFu,0xFFFFFFFFu,
                                 0xFFFFFFFFu,0xFFFFFFFFu,0xFFFFFFFFu,0xFFFFFFFFu};
__device__ unsigned g_mxk[Bb] = {0,0,0,0,0,0,0,0};

// ---------------- data scratch (fully rewritten every launch) -----------------
__device__ __align__(16) float4 g_partial4[Bb][16][C4];
__device__ __align__(16) float  g_xsum[Bb][Cc];
__device__ __align__(16) float  g_kp[Bb][16][Cc];   // ksum column-partials
__device__ __align__(16) float  g_wp[Bb][16][Cc];   // w o-chunk partials
__device__ __align__(16) float  g_up[Bb][16][Cc];   // u partials (+wp folded in)

__device__ __forceinline__ unsigned enc(float f) {
    unsigned u = __float_as_uint(f);
    return (u & 0x80000000u) ? ~u : (u | 0x80000000u);
}
__device__ __forceinline__ float dec(unsigned k) {
    return (k & 0x80000000u) ? __uint_as_float(k ^ 0x80000000u)
                             : __uint_as_float(~k);
}

#define ARRIVE(lineptr)                                               \
    do { __syncthreads();                                             \
         if (t == 0) { __threadfence(); atomicAdd(&(lineptr)->v, 1u); } \
    } while (0)
#define WAITGE(lineptr, tgt)                                          \
    do { if (t == 0) {                                                \
             while (*(volatile const unsigned*)&(lineptr)->v          \
                    < (unsigned)(tgt)) {}                             \
             __threadfence();                                         \
         }                                                            \
         __syncthreads();                                             \
    } while (0)

__global__ void __launch_bounds__(NTHR)
fused_kernel(const float* __restrict__ x,
             const float* __restrict__ conv_w, const float* __restrict__ conv_b,
             const float* __restrict__ q_w,
             const float* __restrict__ k_w,    const float* __restrict__ k_b,
             float* __restrict__ out)
{
    extern __shared__ float dynsh[];
    float* conv_s = dynsh;              // [32 rows of chunk m][512 c]
    float* q_s    = dynsh + 16384;      // [32 rows of chunk m][512 c]
    float* kC     = dynsh + 32768;      // [32 c-local][512 o]  (k_w columns)
    // psum for dot phase aliases conv_s region (weights done by then)
    __shared__ __align__(16) float4 sStag4[4][C4];   // 8 KB colsum staging
    __shared__ __align__(16) float  sXsum[Bb][Cc];   // 16 KB
    __shared__ __align__(16) float  sU[Cc];          // 2 KB
    __shared__ float sXr[Bb][32];
    __shared__ float sRed[Bb][32];
    __shared__ float sTot[32];
    __shared__ float sV[Bb][32];
    __shared__ float sW[Bb][32];
    __shared__ float sdot[64];
    __shared__ unsigned sh_tk;

    const int g    = blockIdx.x;
    const int t    = threadIdx.x;
    const int warp = t >> 5, lane = t & 31;
    const int b_own = g >> 4, s_own = g & 15;
    const int c4t = t & 127, rs = t >> 7;
    const int m = g;                    // mid-chunk id (only valid for g<16)

    // ============ P1: x tile -> registers (+colsum) & weight prefetch ========
    float4 xreg[16];
    {
        const float4* base = reinterpret_cast<const float4*>(x)
                           + ((size_t)(b_own * HW + s_own * 64 + rs * 16)) * C4 + c4t;
        float4 acc = make_float4(0.f, 0.f, 0.f, 0.f);
#pragma unroll
        for (int p = 0; p < 16; ++p) {
            xreg[p] = base[(size_t)p * C4];
            acc.x += xreg[p].x; acc.y += xreg[p].y;
            acc.z += xreg[p].z; acc.w += xreg[p].w;
        }
        sStag4[rs][c4t] = acc;

        if (g < 16) {                   // mid blocks prefetch 3 weight slabs
            const float4* cw4 = reinterpret_cast<const float4*>(conv_w) + m * 4096;
            const float4* qw4 = reinterpret_cast<const float4*>(q_w)    + m * 4096;
            float4* cs4 = reinterpret_cast<float4*>(conv_s);
            float4* qs4 = reinterpret_cast<float4*>(q_s);
#pragma unroll
            for (int i = 0; i < 8; ++i) cs4[t + i * NTHR] = cw4[t + i * NTHR];
#pragma unroll
            for (int i = 0; i < 8; ++i) qs4[t + i * NTHR] = qw4[t + i * NTHR];
            // k_w columns chunk m, transposed into kC[c_local][o]
            const float4* kw4 = reinterpret_cast<const float4*>(k_w);
#pragma unroll
            for (int i = 0; i < 8; ++i) {
                const int f = t + i * NTHR;      // 0..4095
                const int row = f >> 3, seg = f & 7;
                const float4 v = kw4[row * C4 + m * 8 + seg];
                kC[(seg * 4 + 0) * Cc + row] = v.x;
                kC[(seg * 4 + 1) * Cc + row] = v.y;
                kC[(seg * 4 + 2) * Cc + row] = v.z;
                kC[(seg * 4 + 3) * Cc + row] = v.w;
            }
        }
        __syncthreads();
        if (t < C4) {
            float4 a = sStag4[0][t], p1 = sStag4[1][t], p2 = sStag4[2][t], p3 = sStag4[3][t];
            a.x += p1.x + p2.x + p3.x;  a.y += p1.y + p2.y + p3.y;
            a.z += p1.z + p2.z + p3.z;  a.w += p1.w + p2.w + p3.w;
            g_partial4[b_own][s_own][t] = a;
        }
    }
    // colsum ticket: 16th block of each batch reduces Xsum (fixed order)
    __syncthreads();
    if (t == 0) { __threadfence(); sh_tk = atomicAdd(&c_cs[b_own].v, 1u); }
    __syncthreads();
    if (sh_tk == 15u) {
        __threadfence();                // see other blocks' partials
        const float* gp = &g_partial4[0][0][0].x;
        float a = 0.f;
#pragma unroll
        for (int sp = 0; sp < 16; ++sp)
            a += gp[(b_own * 16 + sp) * Cc + t];
        g_xsum[b_own][t] = a;
        __syncthreads();
        if (t == 0) { __threadfence(); atomicAdd(&c_xs.v, 1u); }
    }

    // ============ mid blocks (0..15): fused 3-stage chain for chunk m ========
    if (g < 16) {
        // ---- stage 1: xr rows chunk m (all b) + ksum column-partials kp -----
        WAITGE(&c_xs, 8);
        {
            float4* sXs4 = reinterpret_cast<float4*>(sXsum);
#pragma unroll
            for (int i = 0; i < 2; ++i)
                sXs4[t + i * NTHR] = reinterpret_cast<const float4*>(g_xsum)[t + i * NTHR];
        }
        __syncthreads();
        {   // 256 (b,row) tasks over 16 warps, lane-split dot + shuffle reduce
            const float4* cs4 = reinterpret_cast<const float4*>(conv_s);
            const float4* sXs4 = reinterpret_cast<const float4*>(sXsum);
#pragma unroll
            for (int i = 0; i < 16; ++i) {
                const int task = warp * 16 + i;
                const int b = task >> 5, r = task & 31;
                float acc = 0.f;
#pragma unroll
                for (int k = 0; k < 4; ++k) {
                    const float4 wv = cs4[r * C4 + lane + 32 * k];
                    const float4 xv = sXs4[b * C4 + lane + 32 * k];
                    acc += wv.x * xv.x + wv.y * xv.y + wv.z * xv.z + wv.w * xv.w;
                }
#pragma unroll
                for (int off = 16; off; off >>= 1)
                    acc += __shfl_xor_sync(0xffffffffu, acc, off);
                if (lane == 0)
                    sXr[b][r] = acc + (float)HW * conv_b[m * 32 + r]
                              + sXsum[b][m * 32 + r];
            }
        }
        __syncthreads();
        {   // kp[b][m][o] = sum_{c in chunk} k_w[o][m*32+c] * xr[b][c-local]
            const int o = t;
            float acc[Bb];
#pragma unroll
            for (int b = 0; b < Bb; ++b) acc[b] = 0.f;
#pragma unroll
            for (int c = 0; c < 32; ++c) {
                const float kv = kC[c * Cc + o];
#pragma unroll
                for (int b = 0; b < Bb; ++b) acc[b] += kv * sXr[b][c];
            }
#pragma unroll
            for (int b = 0; b < Bb; ++b) g_kp[b][m][o] = acc[b];
        }
        ARRIVE(&c_kp);

        // ---- stage 2: assemble v rows chunk m; wp[b][m][c] = q_w^T v --------
        WAITGE(&c_kp, 16);
        if (t < 256) {
            const int b = t >> 5, oo = t & 31;
            float a = 0.f;
#pragma unroll
            for (int jj = 0; jj < 16; ++jj) a += g_kp[b][jj][m * 32 + oo];
            sRed[b][oo] = a;
        }
        __syncthreads();
        if (t < 32) {
            float a = 0.f;
#pragma unroll
            for (int b = 0; b < Bb; ++b) a += sRed[b][t];
            sTot[t] = a + 7.0f * (float)HW * k_b[m * 32 + t];
        }
        __syncthreads();
        if (t < 256) {
            const int b = t >> 5, oo = t & 31;
            sV[b][oo] = sTot[oo] - sRed[b][oo];
        }
        __syncthreads();
        {
            const int c = t;
            float acc[Bb];
#pragma unroll
            for (int b = 0; b < Bb; ++b) acc[b] = 0.f;
#pragma unroll
            for (int oo = 0; oo < 32; ++oo) {
                const float qv = q_s[oo * Cc + c];
#pragma unroll
                for (int b = 0; b < Bb; ++b) acc[b] += qv * sV[b][oo];
            }
#pragma unroll
            for (int b = 0; b < Bb; ++b) g_wp[b][m][c] = acc[b];
        }
        ARRIVE(&c_wp);

        // ---- stage 3: w rows chunk m; up'[b][m][c] = conv^T w + wp ----------
        WAITGE(&c_wp, 16);
        if (t < 256) {
            const int b = t >> 5, oo = t & 31;
            float a = 0.f;
#pragma unroll
            for (int jj = 0; jj < 16; ++jj) a += g_wp[b][jj][m * 32 + oo];
            sW[b][oo] = a;
        }
        __syncthreads();
        {
            const int c = t;
            float acc[Bb];
#pragma unroll
            for (int b = 0; b < Bb; ++b) acc[b] = 0.f;
#pragma unroll
            for (int oo = 0; oo < 32; ++oo) {
                const float cv = conv_s[oo * Cc + c];
#pragma unroll
                for (int b = 0; b < Bb; ++b) acc[b] += cv * sW[b][oo];
            }
#pragma unroll
            for (int b = 0; b < Bb; ++b)
                g_up[b][m][c] = acc[b] + g_wp[b][m][c];   // fold +w residual
        }
        ARRIVE(&c_up);
    }

    // ============ all blocks: u assemble + dot ===============================
    WAITGE(&c_up, 16);
    {
        float a = 0.f;
#pragma unroll
        for (int jj = 0; jj < 16; ++jj) a += g_up[b_own][jj][t];
        sU[t] = a;
        __syncthreads();

        float* psum = dynsh;            // [64][C4], aliases conv_s (now free)
        const float4 uv = reinterpret_cast<const float4*>(sU)[c4t];
#pragma unroll
        for (int p = 0; p < 16; ++p) {
            const float4 xv = xreg[p];
            psum[(rs * 16 + p) * C4 + c4t] =
                xv.x * uv.x + xv.y * uv.y + xv.z * uv.z + xv.w * uv.w;
        }
        __syncthreads();
#pragma unroll
        for (int rr = 0; rr < 4; ++rr) {
            const int row = warp * 4 + rr;
            float sm = psum[row * C4 + lane] + psum[row * C4 + lane + 32]
                     + psum[row * C4 + lane + 64] + psum[row * C4 + lane + 96];
#pragma unroll
            for (int off = 16; off; off >>= 1)
                sm += __shfl_xor_sync(0xffffffffu, sm, off);
            if (lane == 0) sdot[row] = sm;
        }
    }
    __syncthreads();
    if (warp == 0) {
        float v0 = sdot[lane], v1 = sdot[lane + 32];
        float mn = fminf(v0, v1), mx = fmaxf(v0, v1);
#pragma unroll
        for (int off = 16; off; off >>= 1) {
            mn = fminf(mn, __shfl_xor_sync(0xffffffffu, mn, off));
            mx = fmaxf(mx, __shfl_xor_sync(0xffffffffu, mx, off));
        }
        if (lane == 0) {
            atomicMin(&g_mnk[b_own], enc(mn));
            atomicMax(&g_mxk[b_own], enc(mx));
        }
    }
    // distributed epilogue: wait own batch's 16 minmax arrivals
    ARRIVE(&c_ep[b_own]);
    WAITGE(&c_ep[b_own], 16);
    if (t < 64) {
        const float mn = dec(g_mnk[b_own]);
        const float mx = dec(g_mxk[b_own]);
        const float z = ((sdot[t] - mn) / (mx - mn) - 0.65f) / 0.15f;
        out[b_own * HW + s_own * 64 + t] = 1.0f / (1.0f + __expf(-z));
    }
    // reset chain: 128th arrival resets all state (never polled)
    __syncthreads();
    if (t == 0) {
        unsigned old = atomicAdd(&c_fin.v, 1u);
        if (old == (unsigned)NBLK - 1u) {
#pragma unroll
            for (int i = 0; i < 8; ++i) { c_cs[i].v = 0u; c_ep[i].v = 0u; }
            c_xs.v = 0u; c_kp.v = 0u; c_wp.v = 0u; c_up.v = 0u; c_fin.v = 0u;
#pragma unroll
            for (int b = 0; b < Bb; ++b) { g_mnk[b] = 0xFFFFFFFFu; g_mxk[b] = 0u; }
            __threadfence();
        }
    }
}

// ---------------------------------------------------------------------------
extern "C" void kernel_launch(void* const* d_in, const int* in_sizes, int n_in,
                              void* d_out, int out_size) {
    const float* x      = (const float*)d_in[0];
    const float* conv_w = (const float*)d_in[1];
    const float* conv_b = (const float*)d_in[2];
    const float* q_w    = (const float*)d_in[3];
    // d_in[4] = q_b: per-batch constant, cancels in min/max normalization.
    const float* k_w    = (const float*)d_in[5];
    const float* k_b    = (const float*)d_in[6];
    float* out = (float*)d_out;

    cudaFuncSetAttribute(fused_kernel,
                         cudaFuncAttributeMaxDynamicSharedMemorySize,
                         DYN_BYTES);
    fused_kernel<<<NBLK, NTHR, DYN_BYTES>>>(x, conv_w, conv_b, q_w, k_w, k_b, out);
}

// round 15
// speedup vs baseline: 1.3007x; 1.3007x over previous
#include <cuda_runtime.h>

#define Bb   8
#define HW   1024
#define Cc   512
#define C4   128
#define NBLK 128
#define NTHR 512
#define DYN_BYTES (64 * 1024 + 32 * 1024)   // wbuf (64KB) + psum (32KB)

// ---------------- sync state: one counter per 128-B line ---------------------
struct alignas(128) Line { unsigned v; unsigned pad[31]; };
__device__ Line cnt0[8];    // P1 arrivals, per batch (16 each)
__device__ Line cnt1[4];    // P2a arrivals (32 total, 8/line)
__device__ Line cnt2[4];    // P2b arrivals (32)
__device__ Line cnt3[4];    // P3 arrivals (32)
__device__ Line cnt4[2];    // P4 arrivals (16, 8/line)
__device__ Line cnt6[1];    // P5 arrivals (16)
__device__ Line cnt7[8];    // epilogue arrivals, per batch (16 each)
__device__ Line c_fin;      // 128 arrivals; 128th resets (never polled)
__device__ unsigned g_mnk[Bb] = {0xFFFFFFFFu,0xFFFFFFFFu,0xFFFFFFFFu,0xFFFFFFFFu,
                                 0xFFFFFFFFu,0xFFFFFFFFu,0xFFFFFFFFu,0xFFFFFFFFu};
__device__ unsigned g_mxk[Bb] = {0,0,0,0,0,0,0,0};

// ---------------- data scratch (fully rewritten every launch) ----------------
__device__ __align__(16) float4 g_partial[Bb][16][C4];
__device__ __align__(16) float4 g_xsum4[Bb][C4];
__device__ __align__(16) float  g_xr[Bb][Cc];
__device__ __align__(16) float  g_ksum[Bb][Cc];
__device__ __align__(16) float  g_wpart[16][Bb][Cc];
__device__ __align__(16) float  g_w[Bb][Cc];
__device__ __align__(16) float  g_upart[16][Bb][Cc];

__device__ __forceinline__ unsigned ldv(const unsigned* p) {
    return *(volatile const unsigned*)p;
}
__device__ __forceinline__ unsigned enc(float f) {
    unsigned u = __float_as_uint(f);
    return (u & 0x80000000u) ? ~u : (u | 0x80000000u);
}
__device__ __forceinline__ float dec(unsigned k) {
    return (k & 0x80000000u) ? __uint_as_float(k ^ 0x80000000u)
                             : __uint_as_float(~k);
}

// arrive: t==0 (after block sync) releases + bumps one line
#define ARRIVE_LINE(lineptr)                                          \
    do { __syncthreads();                                             \
         if (t == 0) { __threadfence(); atomicAdd(&(lineptr)->v, 1u); } \
    } while (0)
// wait until sum of n lines >= tgt
#define WAIT_LINES(arr, n, tgt)                                       \
    do { if (t == 0) {                                                \
             unsigned s_;                                             \
             do { s_ = 0;                                             \
                  _Pragma("unroll")                                   \
                  for (int i_ = 0; i_ < (n); ++i_) s_ += ldv(&(arr)[i_].v); \
             } while (s_ < (unsigned)(tgt));                          \
             __threadfence();                                         \
         }                                                            \
         __syncthreads();                                             \
    } while (0)

__global__ void __launch_bounds__(NTHR)
fused_kernel(const float* __restrict__ x,
             const float* __restrict__ conv_w, const float* __restrict__ conv_b,
             const float* __restrict__ q_w,
             const float* __restrict__ k_w,    const float* __restrict__ k_b,
             float* __restrict__ out)
{
    extern __shared__ float dynsh[];
    float* wbuf = dynsh;                         // 16384 floats (64 KB)
    float* psum = dynsh + 16384;                 // 8192 floats (32 KB): [64][128]
    __shared__ __align__(16) float shA[Bb][Cc];  // 16 KB
    __shared__ __align__(16) float shB[Cc];      // 2 KB
    __shared__ float sdot[64];
    __shared__ float shW[Bb][32];

    const int g    = blockIdx.x;
    const int t    = threadIdx.x;
    const int warp = t >> 5, lane = t & 31;
    const int b_own = g >> 4, s_own = g & 15;
    const int c4 = t & 127, rs = t >> 7;

    // ================= P1: x tile -> REGISTERS (+colsum) & weight prefetch ===
    float4 xreg[16];
    {
        const float4* base = reinterpret_cast<const float4*>(x)
                           + ((size_t)(b_own * HW + s_own * 64 + rs * 16)) * C4 + c4;
        float4 acc = make_float4(0.f, 0.f, 0.f, 0.f);
#pragma unroll
        for (int p = 0; p < 16; ++p) {
            xreg[p] = base[(size_t)p * C4];
            acc.x += xreg[p].x; acc.y += xreg[p].y;
            acc.z += xreg[p].z; acc.w += xreg[p].w;
        }
        float4* shP = reinterpret_cast<float4*>(shA);   // [4][128]
        shP[rs * C4 + c4] = acc;

        // weight prefetch into smem (overlaps x loads)
        float4* wb4 = reinterpret_cast<float4*>(wbuf);
        if (g >= 32 && g < 64) {            // A: conv_w rows [(g-32)*16, +16)
            const float4* src = reinterpret_cast<const float4*>(conv_w) + (g - 32) * 2048;
#pragma unroll
            for (int i = 0; i < 4; ++i) wb4[t + i * NTHR] = src[t + i * NTHR];
        } else if (g >= 64 && g < 96) {     // B: k_w rows [(g-64)*16, +16)
            const float4* src = reinterpret_cast<const float4*>(k_w) + (g - 64) * 2048;
#pragma unroll
            for (int i = 0; i < 4; ++i) wb4[t + i * NTHR] = src[t + i * NTHR];
        } else if (g < 16) {                // C: q_w rows [g*32, +32)
            const float4* src = reinterpret_cast<const float4*>(q_w) + g * 4096;
#pragma unroll
            for (int i = 0; i < 8; ++i) wb4[t + i * NTHR] = src[t + i * NTHR];
        } else if (g >= 16 && g < 32) {     // D: conv_w rows [(g-16)*32, +32)
            const float4* src = reinterpret_cast<const float4*>(conv_w) + (g - 16) * 4096;
#pragma unroll
            for (int i = 0; i < 8; ++i) wb4[t + i * NTHR] = src[t + i * NTHR];
        }
        __syncthreads();
        if (t < C4) {
            float4* shP2 = reinterpret_cast<float4*>(shA);
            float4 a = shP2[t], p1 = shP2[C4 + t], p2 = shP2[2 * C4 + t], p3 = shP2[3 * C4 + t];
            a.x += p1.x + p2.x + p3.x;  a.y += p1.y + p2.y + p3.y;
            a.z += p1.z + p2.z + p3.z;  a.w += p1.w + p2.w + p3.w;
            g_partial[b_own][s_own][t] = a;
        }
    }
    ARRIVE_LINE(&cnt0[b_own]);

    // ================= group A (32..63): Xsum reduce + conv matvec ===========
    if (g >= 32 && g < 64) {
        const int a = g - 32;
        WAIT_LINES(&cnt0[a >> 2], 1, 16);    // only needs its batch's partials
        {   // P2a: float4 outputs o in [a*32, a*32+32), all in batch a>>2
            const int o = a * 32 + (t >> 4), s = t & 15;
            const int bb = o >> 7, cc4 = o & 127;
            float4 v = g_partial[bb][s][cc4];
#pragma unroll
            for (int off = 8; off; off >>= 1) {
                v.x += __shfl_xor_sync(0xffffffffu, v.x, off);
                v.y += __shfl_xor_sync(0xffffffffu, v.y, off);
                v.z += __shfl_xor_sync(0xffffffffu, v.z, off);
                v.w += __shfl_xor_sync(0xffffffffu, v.w, off);
            }
            if (s == 0) g_xsum4[bb][cc4] = v;
        }
        ARRIVE_LINE(&cnt1[a & 3]);
        WAIT_LINES(cnt1, 4, 32);
        {   // P2b: xr = conv_w @ Xsum + HW*conv_b + Xsum
            float4* shA4 = reinterpret_cast<float4*>(shA);
            const float4* gx4 = reinterpret_cast<const float4*>(g_xsum4);
#pragma unroll
            for (int i = 0; i < 2; ++i) shA4[t + i * NTHR] = gx4[t + i * NTHR];
            __syncthreads();

            const int o = a * 16 + warp;
            float acc[Bb];
#pragma unroll
            for (int b = 0; b < Bb; ++b) acc[b] = 0.f;
#pragma unroll
            for (int k = 0; k < 16; ++k) {
                const int c = lane + 32 * k;
                const float wv = wbuf[warp * Cc + c];
#pragma unroll
                for (int b = 0; b < Bb; ++b) acc[b] += wv * shA[b][c];
            }
#pragma unroll
            for (int b = 0; b < Bb; ++b)
#pragma unroll
                for (int off = 16; off; off >>= 1)
                    acc[b] += __shfl_xor_sync(0xffffffffu, acc[b], off);
            if (lane == 0) {
                const float cb = (float)HW * conv_b[o];
#pragma unroll
                for (int b = 0; b < Bb; ++b)
                    g_xr[b][o] = acc[b] + cb + shA[b][o];
            }
        }
        ARRIVE_LINE(&cnt2[a & 3]);
    }

    // ================= group B (64..95): Ksum matvec =========================
    if (g >= 64 && g < 96) {
        const int bbk = g - 64;
        WAIT_LINES(cnt2, 4, 32);
        {
            float4* shA4 = reinterpret_cast<float4*>(shA);
            const float4* gxr4 = reinterpret_cast<const float4*>(g_xr);
#pragma unroll
            for (int i = 0; i < 2; ++i) shA4[t + i * NTHR] = gxr4[t + i * NTHR];
            __syncthreads();

            const int o = bbk * 16 + warp;
            float acc[Bb];
#pragma unroll
            for (int b = 0; b < Bb; ++b) acc[b] = 0.f;
#pragma unroll
            for (int k = 0; k < 16; ++k) {
                const int c = lane + 32 * k;
                const float wv = wbuf[warp * Cc + c];
#pragma unroll
                for (int b = 0; b < Bb; ++b) acc[b] += wv * shA[b][c];
            }
#pragma unroll
            for (int b = 0; b < Bb; ++b)
#pragma unroll
                for (int off = 16; off; off >>= 1)
                    acc[b] += __shfl_xor_sync(0xffffffffu, acc[b], off);
            if (lane == 0) {
                const float kb = (float)HW * k_b[o];
#pragma unroll
                for (int b = 0; b < Bb; ++b)
                    g_ksum[b][o] = acc[b] + kb;
            }
        }
        ARRIVE_LINE(&cnt3[bbk & 3]);
    }

    // ================= group C (0..15): w partials ===========================
    if (g < 16) {
        WAIT_LINES(cnt3, 4, 32);
        float tot = 0.f;
#pragma unroll
        for (int b = 0; b < Bb; ++b) tot += g_ksum[b][t];
        shB[t] = tot;
        __syncthreads();
#pragma unroll
        for (int i = 0; i < Bb; ++i) {
            const int idx = t + i * NTHR;
            const int b = idx >> 9, c = idx & 511;
            shA[b][c] = shB[c] - g_ksum[b][c];
        }
        __syncthreads();

        float acc[Bb];
#pragma unroll
        for (int b = 0; b < Bb; ++b) acc[b] = 0.f;
#pragma unroll
        for (int oo = 0; oo < 32; ++oo) {
            const int o = g * 32 + oo;
            const float wv = wbuf[oo * Cc + t];
#pragma unroll
            for (int b = 0; b < Bb; ++b) acc[b] += wv * shA[b][o];
        }
#pragma unroll
        for (int b = 0; b < Bb; ++b) g_wpart[g][b][t] = acc[b];
        ARRIVE_LINE(&cnt4[g & 1]);
    }

    // ================= group D (16..31): w reduce (o-chunk) + u partial ======
    if (g >= 16 && g < 32) {
        const int j = g - 16;
        WAIT_LINES(cnt4, 2, 16);
        {   // inline reduce of w over its o-chunk [j*32, +32), all b
            const int p = t >> 1, h = t & 1;       // p: 0..255 = (b,oo)
            const int b = p >> 5, oo = p & 31;
            float s = 0.f;
#pragma unroll
            for (int jj = 0; jj < 8; ++jj)
                s += g_wpart[h * 8 + jj][b][j * 32 + oo];
            s += __shfl_xor_sync(0xffffffffu, s, 1);
            if (h == 0) { shW[b][oo] = s; g_w[b][j * 32 + oo] = s; }
            __syncthreads();
        }
        {   // u partial: conv_w^T over o-chunk
            float acc[Bb];
#pragma unroll
            for (int b = 0; b < Bb; ++b) acc[b] = 0.f;
#pragma unroll
            for (int oo = 0; oo < 32; ++oo) {
                const float wv = wbuf[oo * Cc + t];
#pragma unroll
                for (int b = 0; b < Bb; ++b) acc[b] += wv * shW[b][oo];
            }
#pragma unroll
            for (int b = 0; b < Bb; ++b) g_upart[j][b][t] = acc[b];
        }
        ARRIVE_LINE(&cnt6[0]);
    }

    // ================= all blocks: P6 dot + epilogue =========================
    WAIT_LINES(cnt6, 1, 16);
    {
        // u[t] = sum_j upart[j][b][t] + w[b][t]   (the +w residual term)
        float a = g_w[b_own][t];
#pragma unroll
        for (int jj = 0; jj < 16; ++jj) a += g_upart[jj][b_own][t];
        shB[t] = a;
        __syncthreads();

        const float4 uv = reinterpret_cast<const float4*>(shB)[c4];
#pragma unroll
        for (int p = 0; p < 16; ++p) {
            const float4 xv = xreg[p];
            psum[(rs * 16 + p) * C4 + c4] =
                xv.x * uv.x + xv.y * uv.y + xv.z * uv.z + xv.w * uv.w;
        }
        __syncthreads();

        // row reduce: warp handles 4 rows, 128 partials each
#pragma unroll
        for (int rr = 0; rr < 4; ++rr) {
            const int row = warp * 4 + rr;
            float s = psum[row * C4 + lane] + psum[row * C4 + lane + 32]
                    + psum[row * C4 + lane + 64] + psum[row * C4 + lane + 96];
#pragma unroll
            for (int off = 16; off; off >>= 1)
                s += __shfl_xor_sync(0xffffffffu, s, off);
            if (lane == 0) sdot[row] = s;
        }
    }
    __syncthreads();
    if (warp == 0) {
        float v0 = sdot[lane], v1 = sdot[lane + 32];
        float mn = fminf(v0, v1), mx = fmaxf(v0, v1);
#pragma unroll
        for (int off = 16; off; off >>= 1) {
            mn = fminf(mn, __shfl_xor_sync(0xffffffffu, mn, off));
            mx = fmaxf(mx, __shfl_xor_sync(0xffffffffu, mx, off));
        }
        if (lane == 0) {
            atomicMin(&g_mnk[b_own], enc(mn));
            atomicMax(&g_mxk[b_own], enc(mx));
        }
    }
    ARRIVE_LINE(&cnt7[b_own]);
    WAIT_LINES(&cnt7[b_own], 1, 16);

    if (t < 64) {
        const float mn = dec(g_mnk[b_own]);
        const float mx = dec(g_mxk[b_own]);
        const float inv = 1.0f / (mx - mn);
        const float z = ((sdot[t] - mn) * inv - 0.65f) / 0.15f;
        out[b_own * HW + s_own * 64 + t] = 1.0f / (1.0f + __expf(-z));
    }

    // ======= tail: never-polled reset — 128th arrival resets everything ======
    __syncthreads();
    if (t == 0) {
        unsigned old = atomicAdd(&c_fin.v, 1u);
        if (old == (unsigned)NBLK - 1u) {
#pragma unroll
            for (int i = 0; i < 8;  ++i) { cnt0[i].v = 0u; cnt7[i].v = 0u; }
#pragma unroll
            for (int i = 0; i < 4;  ++i) { cnt1[i].v = 0u; cnt2[i].v = 0u; cnt3[i].v = 0u; }
#pragma unroll
            for (int i = 0; i < 2;  ++i) cnt4[i].v = 0u;
            cnt6[0].v = 0u;
            c_fin.v = 0u;
#pragma unroll
            for (int b = 0; b < Bb; ++b) { g_mnk[b] = 0xFFFFFFFFu; g_mxk[b] = 0u; }
            __threadfence();
        }
    }
}

// ---------------------------------------------------------------------------
extern "C" void kernel_launch(void* const* d_in, const int* in_sizes, int n_in,
                              void* d_out, int out_size) {
    const float* x      = (const float*)d_in[0];
    const float* conv_w = (const float*)d_in[1];
    const float* conv_b = (const float*)d_in[2];
    const float* q_w    = (const float*)d_in[3];
    // d_in[4] = q_b: per-batch constant, cancels in min/max normalization.
    const float* k_w    = (const float*)d_in[5];
    const float* k_b    = (const float*)d_in[6];
    float* out = (float*)d_out;

    cudaFuncSetAttribute(fused_kernel,
                         cudaFuncAttributeMaxDynamicSharedMemorySize,
                         DYN_BYTES);
    fused_kernel<<<NBLK, NTHR, DYN_BYTES>>>(x, conv_w, conv_b, q_w, k_w, k_b, out);
}